// round 11
// baseline (speedup 1.0000x reference)
#include <cuda_runtime.h>
#include <cstdint>

#define NV   64
#define NQ   504            // quads per batch (2016/4)
#define F4B  1512           // float4 per batch
#define TPB  512
#define NW   16             // warps per block
#define MAXB 16             // max batches per CTA (ceil(4096/296)=14)

__global__ __launch_bounds__(TPB, 2) void score_kernel(
    const float* __restrict__ views,     // [B, 64, 7]
    const float* __restrict__ pairs,     // [B, 2016, 3]
    const float* __restrict__ s_a1,
    const float* __restrict__ s_a2,
    const float* __restrict__ s_gsd,
    const float* __restrict__ s_scale,
    const float* __restrict__ s_nrm,
    const float* __restrict__ s_dist,
    float* __restrict__ out,             // [B]
    int B)
{
    __shared__ float w[MAXB][NV];
    __shared__ float warpsum[MAXB][NW];

    const int tid = threadIdx.x;
    const int bx  = blockIdx.x;
    const int gsz = gridDim.x;

    int nb = (B - bx + gsz - 1) / gsz;
    if (nb > MAXB) nb = MAXB;

    // ---- per-thread quad slot: ONE quad per batch ----
    const int qt = (tid < NQ) ? tid : 0;
    const float vm = (tid < NQ) ? 1.0f : 0.0f;
    const float4* pbase = (const float4*)pairs + 3 * qt;

    // ---- fire loads for batches 0 and 1 immediately (depth-2 pipeline) ----
    const float4* pA = pbase + (size_t)bx * F4B;
    float4 A0 = __ldcs(pA + 0);
    float4 A1 = __ldcs(pA + 1);
    float4 A2 = __ldcs(pA + 2);
    float4 B0, B1, B2;
    if (nb > 1) {
        const float4* pB = pbase + (size_t)(bx + gsz) * F4B;
        B0 = __ldcs(pB + 0);
        B1 = __ldcs(pB + 1);
        B2 = __ldcs(pB + 2);
    }

    // ---- scalar params ----
    const float L2E = 1.4426950408889634f;
    const float a1 = *s_a1;
    const float a2 = *s_a2;
    const float c_a1 = -0.5f * L2E / (a1 * a1);
    const float c_a2 = -0.5f * L2E / (a2 * a2);
    const float sc = *s_scale;
    const float c_sc = -0.5f * L2E / (sc * sc);
    const float TH = 20.0f / 90.0f;

    // ---- per-view weights for all owned batches (overlap in-flight loads) --
    {
        const float gs = *s_gsd;   const float c_gsd  = -0.5f * L2E / (gs * gs);
        const float ns = *s_nrm;   const float c_nrm  = -0.5f * L2E / (ns * ns);
        const float ds = *s_dist;  const float c_dist = -0.5f * L2E / (ds * ds);
        for (int e = tid; e < nb * NV; e += TPB) {
            int t = e >> 6;
            int v = e & 63;
            const float* vr = views + ((size_t)(bx + t * gsz) * NV + v) * 7;
            float v0 = vr[0];
            float x4 = vr[4];
            float x5 = vr[5];
            float x6 = vr[6];
            float m  = (v0 == 1.0f) ? 1.0f : 0.0f;
            float x4sq = x4 * x4;
            float arg = fmaf(x4sq * x4sq, c_gsd,
                        fmaf(x5 * x5,     c_nrm,
                             (x6 * x6) *  c_dist));
            w[t][v] = m * exp2f(arg);
        }
    }

    // ---- (i,j) decode: one quad slot, once per CTA lifetime ----
    int i0, j0;
    {
        int p = 4 * qt;
        int i = (int)((127.0f - sqrtf((float)(16129 - 8 * p))) * 0.5f);
        while (p < ((i * (127 - i)) >> 1)) --i;
        while (p >= (((i + 1) * (126 - i)) >> 1)) ++i;
        i0 = i; j0 = p - ((i * (127 - i)) >> 1) + i + 1;
    }

    __syncthreads();   // w[] visible

    // compute 4 pairs from extracted scalars, accumulate into warpsum[t]
    #define COMPUTE_STORE(t, pm, av, sv)                                       \
    {                                                                          \
        float acc = 0.0f;                                                      \
        int i = i0, j = j0;                                                    \
        const float* wr = w[t];                                                \
        _Pragma("unroll")                                                      \
        for (int k = 0; k < 4; ++k) {                                          \
            float a = av[k];                                                   \
            float sx = sv[k];                                                  \
            float m = (a == TH) ? 0.0f : pm[k];                                \
            float ca = (a < TH) ? c_a1 : c_a2;                                 \
            float arg = fmaf(a * a, ca, (sx * sx) * c_sc);                     \
            acc = fmaf(m * exp2f(arg), wr[i] * wr[j], acc);                    \
            ++j;                                                               \
            if (j == NV) { ++i; j = i + 1; }                                   \
        }                                                                      \
        _Pragma("unroll")                                                      \
        for (int o = 16; o > 0; o >>= 1)                                       \
            acc += __shfl_down_sync(0xffffffffu, acc, o);                      \
        if ((tid & 31) == 0) warpsum[t][tid >> 5] = acc;                       \
    }

    #define EXTRACT(f0, f1, f2, pm, av, sv)                                    \
        float pm[4] = { ((f0).x != 0.0f) ? vm : 0.0f,                          \
                        ((f0).w != 0.0f) ? vm : 0.0f,                          \
                        ((f1).z != 0.0f) ? vm : 0.0f,                          \
                        ((f2).y != 0.0f) ? vm : 0.0f };                        \
        float av[4] = { (f0).y, (f1).x, (f1).w, (f2).z };                      \
        float sv[4] = { (f0).z, (f1).y, (f2).x, (f2).w };

    // ---- mainloop: 2x unrolled so A/B alternate roles without reg swaps ----
    for (int t = 0; t < nb; t += 2) {
        {   // even iteration: current batch in A; refill A with t+2
            EXTRACT(A0, A1, A2, pm, av, sv);
            if (t + 2 < nb) {
                const float4* pn = pbase + (size_t)(bx + (t + 2) * gsz) * F4B;
                A0 = __ldcs(pn + 0);
                A1 = __ldcs(pn + 1);
                A2 = __ldcs(pn + 2);
            }
            COMPUTE_STORE(t, pm, av, sv);
        }
        if (t + 1 >= nb) break;
        {   // odd iteration: current batch in B; refill B with t+3
            EXTRACT(B0, B1, B2, pm, av, sv);
            if (t + 3 < nb) {
                const float4* pn = pbase + (size_t)(bx + (t + 3) * gsz) * F4B;
                B0 = __ldcs(pn + 0);
                B1 = __ldcs(pn + 1);
                B2 = __ldcs(pn + 2);
            }
            COMPUTE_STORE(t + 1, pm, av, sv);
        }
    }
    #undef EXTRACT
    #undef COMPUTE_STORE

    __syncthreads();   // warpsum visible

    // ---- fused epilogue: 256 threads reduce up to 16 batches x 16 partials --
    if (tid < 256) {
        const int bb = tid >> 4;
        const int k  = tid & 15;
        float p = (bb < nb) ? warpsum[bb][k] : 0.0f;
        p += __shfl_down_sync(0xffffffffu, p, 8, 16);
        p += __shfl_down_sync(0xffffffffu, p, 4, 16);
        p += __shfl_down_sync(0xffffffffu, p, 2, 16);
        p += __shfl_down_sync(0xffffffffu, p, 1, 16);
        if (k == 0 && bb < nb) out[bx + bb * gsz] = p;
    }
}

extern "C" void kernel_launch(void* const* d_in, const int* in_sizes, int n_in,
                              void* d_out, int out_size) {
    const float* views  = (const float*)d_in[0];
    const float* pairs  = (const float*)d_in[1];
    // d_in[2] = point_attribute (unused by reference computation)
    const float* a1     = (const float*)d_in[3];
    const float* a2     = (const float*)d_in[4];
    const float* gsd    = (const float*)d_in[5];
    const float* scale  = (const float*)d_in[6];
    const float* nrm    = (const float*)d_in[7];
    const float* dist   = (const float*)d_in[8];
    float* out = (float*)d_out;

    int B = in_sizes[0] / (NV * 7);
    int grid = 296;                       // 148 SMs x 2 resident 512-thr CTAs
    if (grid > B) grid = B;

    score_kernel<<<grid, TPB>>>(views, pairs, a1, a2, gsd, scale, nrm, dist,
                                out, B);
}

// round 12
// speedup vs baseline: 1.1117x; 1.1117x over previous
#include <cuda_runtime.h>
#include <cstdint>

#define NV   64
#define HQ   252            // quads per half-batch stage
#define F4S  756            // float4 per half-batch stage
#define F4B  1512           // float4 per batch
#define BATCH_BYTES 24192
#define NLINES 189          // 24192 / 128
#define TPB  256
#define MAXB 8              // max batches per CTA (ceil(4096/592)=7)

__global__ __launch_bounds__(TPB, 4) void score_kernel(
    const float* __restrict__ views,     // [B, 64, 7]
    const float* __restrict__ pairs,     // [B, 2016, 3]
    const float* __restrict__ s_a1,
    const float* __restrict__ s_a2,
    const float* __restrict__ s_gsd,
    const float* __restrict__ s_scale,
    const float* __restrict__ s_nrm,
    const float* __restrict__ s_dist,
    float* __restrict__ out,             // [B]
    int B)
{
    __shared__ float w[MAXB][NV];
    __shared__ float warpsum[MAXB][TPB / 32];

    const int tid = threadIdx.x;
    const int bx  = blockIdx.x;
    const int gsz = gridDim.x;

    int nb = (B - bx + gsz - 1) / gsz;
    if (nb > MAXB) nb = MAXB;

    // ---- scalar params ----
    const float L2E = 1.4426950408889634f;
    const float a1 = *s_a1;
    const float a2 = *s_a2;
    const float c_a1 = -0.5f * L2E / (a1 * a1);
    const float c_a2 = -0.5f * L2E / (a2 * a2);
    const float sc = *s_scale;
    const float c_sc = -0.5f * L2E / (sc * sc);
    const float TH = 20.0f / 90.0f;

    // ---- per-thread pair slot (shared by all batches) ----
    const int qt = (tid < HQ) ? tid : 0;
    const float vm = (tid < HQ) ? 1.0f : 0.0f;
    const char* pair_bytes = (const char*)pairs;

    // L2 prefetch one whole batch: 189 lines, one per thread
    #define PREFETCH_BATCH(t_)                                                 \
    {                                                                          \
        if ((t_) < nb && tid < NLINES) {                                       \
            const char* pl = pair_bytes                                        \
                + (size_t)(bx + (t_) * gsz) * BATCH_BYTES + (size_t)tid * 128; \
            asm volatile("prefetch.global.L2 [%0];" :: "l"(pl));               \
        }                                                                      \
    }

    // ---- fire the first demand loads + warmup prefetches immediately ----
    const float4* pbase = (const float4*)pairs + 3 * qt;
    const float4* p0 = pbase + (size_t)bx * F4B;        // batch 0, even half
    float4 c0 = __ldcs(p0 + 0);
    float4 c1 = __ldcs(p0 + 1);
    float4 c2 = __ldcs(p0 + 2);
    PREFETCH_BATCH(1);
    PREFETCH_BATCH(2);

    // ---- per-view weights for all owned batches (overlap in-flight loads) --
    {
        const float gs = *s_gsd;   const float c_gsd  = -0.5f * L2E / (gs * gs);
        const float ns = *s_nrm;   const float c_nrm  = -0.5f * L2E / (ns * ns);
        const float ds = *s_dist;  const float c_dist = -0.5f * L2E / (ds * ds);
        for (int e = tid; e < nb * NV; e += TPB) {
            int t = e >> 6;
            int v = e & 63;
            const float* vr = views + ((size_t)(bx + t * gsz) * NV + v) * 7;
            float v0 = vr[0];
            float x4 = vr[4];
            float x5 = vr[5];
            float x6 = vr[6];
            float m  = (v0 == 1.0f) ? 1.0f : 0.0f;
            float x4sq = x4 * x4;
            float arg = fmaf(x4sq * x4sq, c_gsd,
                        fmaf(x5 * x5,     c_nrm,
                             (x6 * x6) *  c_dist));
            w[t][v] = m * exp2f(arg);
        }
    }

    // ---- (i,j) decode: once per CTA, both half-stage offsets ----
    int i0, j0, i1, j1;
    {
        int p = 4 * qt;
        int i = (int)((127.0f - sqrtf((float)(16129 - 8 * p))) * 0.5f);
        while (p < ((i * (127 - i)) >> 1)) --i;
        while (p >= (((i + 1) * (126 - i)) >> 1)) ++i;
        i0 = i; j0 = p - ((i * (127 - i)) >> 1) + i + 1;
    }
    {
        int p = 4 * (qt + HQ);
        int i = (int)((127.0f - sqrtf((float)(16129 - 8 * p))) * 0.5f);
        while (p < ((i * (127 - i)) >> 1)) --i;
        while (p >= (((i + 1) * (126 - i)) >> 1)) ++i;
        i1 = i; j1 = p - ((i * (127 - i)) >> 1) + i + 1;
    }

    __syncthreads();   // w[] visible

    float acc = 0.0f;

    #define PROC(f0, f1, f2, istart, jstart, wrow)                             \
    {                                                                          \
        int i = (istart), j = (jstart);                                        \
        float pm[4] = { ((f0).x != 0.0f) ? vm : 0.0f,                          \
                        ((f0).w != 0.0f) ? vm : 0.0f,                          \
                        ((f1).z != 0.0f) ? vm : 0.0f,                          \
                        ((f2).y != 0.0f) ? vm : 0.0f };                        \
        float av[4] = { (f0).y, (f1).x, (f1).w, (f2).z };                      \
        float sv[4] = { (f0).z, (f1).y, (f2).x, (f2).w };                      \
        _Pragma("unroll")                                                      \
        for (int k = 0; k < 4; ++k) {                                          \
            float a = av[k];                                                   \
            float sx = sv[k];                                                  \
            float m = (a == TH) ? 0.0f : pm[k];                                \
            float ca = (a < TH) ? c_a1 : c_a2;                                 \
            float arg = fmaf(a * a, ca, (sx * sx) * c_sc);                     \
            float e = exp2f(arg);                                              \
            acc = fmaf(m * e, (wrow)[i] * (wrow)[j], acc);                     \
            ++j;                                                               \
            if (j == NV) { ++i; j = i + 1; }                                   \
        }                                                                      \
    }

    // ---- mainloop: demand loads 1 half-stage ahead; L2 prefetch 2 batches
    //      ahead keeps an unbounded-depth DRAM stream running ----
    for (int t = 0; t < nb; ++t) {
        const float4* pb = pbase + (size_t)(bx + t * gsz) * F4B;

        // deep L2 prefetch for batch t+2 (fire-and-forget)
        PREFETCH_BATCH(t + 2);

        // demand-prefetch odd half of batch t (should hit L2)
        float4 n0 = __ldcs(pb + F4S + 0);
        float4 n1 = __ldcs(pb + F4S + 1);
        float4 n2 = __ldcs(pb + F4S + 2);

        PROC(c0, c1, c2, i0, j0, w[t]);          // even half of batch t

        c0 = n0; c1 = n1; c2 = n2;

        // demand-prefetch even half of batch t+1
        if (t + 1 < nb) {
            const float4* pn = pbase + (size_t)(bx + (t + 1) * gsz) * F4B;
            n0 = __ldcs(pn + 0);
            n1 = __ldcs(pn + 1);
            n2 = __ldcs(pn + 2);
        }

        PROC(c0, c1, c2, i1, j1, w[t]);          // odd half of batch t

        // batch t done: stash warp partials (distinct slots, no sync needed)
        {
            float a = acc;
            #pragma unroll
            for (int o = 16; o > 0; o >>= 1)
                a += __shfl_down_sync(0xffffffffu, a, o);
            if ((tid & 31) == 0) warpsum[t][tid >> 5] = a;
            acc = 0.0f;
        }

        if (t + 1 < nb) { c0 = n0; c1 = n1; c2 = n2; }
    }
    #undef PROC
    #undef PREFETCH_BATCH

    __syncthreads();   // warpsum visible

    // ---- fused epilogue: reduce up to 8 batches x 8 warp-partials ----
    if (tid < 64) {
        const int bb = tid >> 3;
        const int k  = tid & 7;
        float p = (bb < nb) ? warpsum[bb][k] : 0.0f;
        p += __shfl_down_sync(0xffffffffu, p, 4);
        p += __shfl_down_sync(0xffffffffu, p, 2);
        p += __shfl_down_sync(0xffffffffu, p, 1);
        if (k == 0 && bb < nb) out[bx + bb * gsz] = p;
    }
}

extern "C" void kernel_launch(void* const* d_in, const int* in_sizes, int n_in,
                              void* d_out, int out_size) {
    const float* views  = (const float*)d_in[0];
    const float* pairs  = (const float*)d_in[1];
    // d_in[2] = point_attribute (unused by reference computation)
    const float* a1     = (const float*)d_in[3];
    const float* a2     = (const float*)d_in[4];
    const float* gsd    = (const float*)d_in[5];
    const float* scale  = (const float*)d_in[6];
    const float* nrm    = (const float*)d_in[7];
    const float* dist   = (const float*)d_in[8];
    float* out = (float*)d_out;

    int B = in_sizes[0] / (NV * 7);
    int grid = 592;                       // 148 SMs x 4 resident CTAs, 1 wave
    if (grid > B) grid = B;

    score_kernel<<<grid, TPB>>>(views, pairs, a1, a2, gsd, scale, nrm, dist,
                                out, B);
}